// round 4
// baseline (speedup 1.0000x reference)
#include <cuda_runtime.h>
#include <math.h>

// image 2048x2048 -> DWT high (stride-2, 2x2) -> 1024x1024
// pad to 1449x1449 with pad_before=212, center=724
// out[x*64 + t] = (sum_y bilinear(padded, rot_t(x,y))) / global_max, x<1448
#define MDIM  2048
#define HN    1024
#define PDIM  1449
#define PB    212
#define OUTW  1448
#define NA    64
#define CENTERF 724.0f

#define XT 64          // x-tile (output columns per block)
#define YT 64          // y-chunk
#define NCHUNK 23      // ceil(1448/64)
#define TILE_CAP 8704  // >= max (tw|1)*th = 93*92 = 8556

__device__ float    g_pad[PDIM * PDIM];
__device__ unsigned g_maxkey;

// ---------------------------------------------------------------------------
// Kernel A: fused DWT high-pass + zero pad; reset max key.
// ---------------------------------------------------------------------------
__global__ void dwt_pad_kernel(const float* __restrict__ img) {
    int idx = blockIdx.x * blockDim.x + threadIdx.x;
    if (idx == 0) g_maxkey = 0u;
    if (idx >= PDIM * PDIM) return;
    int py = idx / PDIM;
    int px = idx - py * PDIM;
    int iy = py - PB;
    int ix = px - PB;
    float v = 0.0f;
    if ((unsigned)iy < (unsigned)HN && (unsigned)ix < (unsigned)HN) {
        const float2* r0 = (const float2*)(img + (size_t)(2 * iy) * MDIM) + ix;
        const float2* r1 = (const float2*)((const float*)r0 + MDIM);
        float2 a = __ldg(r0);
        float2 b = __ldg(r1);
        v = -0.1384f * a.x + 0.7243f * a.y
            - 0.6038f * b.x + 0.1601f * b.y;
    }
    g_pad[idx] = v;
}

__device__ __forceinline__ unsigned float_key(float f) {
    unsigned u = __float_as_uint(f);
    return (u & 0x80000000u) ? ~u : (u | 0x80000000u);
}

// wrap an index known to lie in (-PDIM, 2*PDIM)
__device__ __forceinline__ int wrap_idx(int i) {
    if (i >= PDIM) i -= PDIM;
    if (i < 0)     i += PDIM;
    return i;
}

// does pixel-index interval [a, b] (len < PDIM, a > -PDIM, b < 2*PDIM)
// intersect the nonzero pixel range [PB, PB+HN-1] = [212,1235] mod PDIM?
__device__ __forceinline__ bool hits_nz(int a, int b) {
    return (a <= -214) || (a <= 1235 && b >= 212) || (b >= 1661);
}

// ---------------------------------------------------------------------------
// Rotate+sum, SMEM-tiled. One block per (angle, 64-column strip); loops over
// 23 y-chunks. Per chunk: load rotated footprint bbox into SMEM (wrap+zero
// applied at load), then branch-free bilinear sampling from SMEM.
// ---------------------------------------------------------------------------
__global__ void __launch_bounds__(512) rotsum_tile_kernel(float* __restrict__ out) {
    __shared__ float tile[TILE_CAP];
    __shared__ float sred[8][65];

    const int t = blockIdx.y;
    float s, c;
    sincosf((float)t, &s, &c);

    const int tid   = threadIdx.x;
    const int lane  = tid & 31;
    const int wid   = tid >> 5;           // 16 warps
    const int col   = tid & 63;           // 0..63 output column within strip
    const int phase = tid >> 6;           // 0..7 y-phase

    const int   xb  = blockIdx.x * XT;
    const float X   = (float)(xb + col);
    const float kx  = CENTERF * (c + s - 1.0f);
    const float ky  = CENTERF * (c - s - 1.0f);
    const float cxk = fmaf(c, X, -kx);    // x_in = s*Y + cxk
    const float syk = fmaf(-s, X, -ky);   // y_in = c*Y + syk

    // strip corner X values for bbox
    const float Xa = (float)xb, Xb = (float)(xb + XT - 1);

    float acc = 0.0f;

    for (int ch = 0; ch < NCHUNK; ch++) {
        const float Ya = (float)(ch * YT);
        const float Yb = Ya + (float)(YT - 1);

        // x_in = c*X + s*Y - kx at 4 corners (linear -> extrema at corners)
        float x00 = c * Xa + s * Ya - kx;
        float x01 = c * Xa + s * Yb - kx;
        float x10 = c * Xb + s * Ya - kx;
        float x11 = c * Xb + s * Yb - kx;
        float y00 = -s * Xa + c * Ya - ky;
        float y01 = -s * Xa + c * Yb - ky;
        float y10 = -s * Xb + c * Ya - ky;
        float y11 = -s * Xb + c * Yb - ky;

        int bx = (int)floorf(fminf(fminf(x00, x01), fminf(x10, x11)));
        int ex = (int)floorf(fmaxf(fmaxf(x00, x01), fmaxf(x10, x11)));
        int by = (int)floorf(fminf(fminf(y00, y01), fminf(y10, y11)));
        int ey = (int)floorf(fmaxf(fmaxf(y00, y01), fmaxf(y10, y11)));

        int tw = (ex - bx + 2) | 1;       // odd pitch -> conflict-free LDS
        int th = ey - by + 2;

        // skip chunks whose footprint is entirely zero (block-uniform)
        if (!hits_nz(bx, ex + 1) || !hits_nz(by, ey + 1)) continue;

        __syncthreads();  // previous chunk's sampling done before overwrite

        // ---- cooperative tile fill (coalesced, wrap+zero at load) ----
        for (int jj = wid; jj < th; jj += 16) {
            int gy = wrap_idx(by + jj);
            bool rnz = (unsigned)(gy - PB) < (unsigned)HN;
            const float* __restrict__ rp = g_pad + (size_t)gy * PDIM;
            float* trow = tile + jj * tw;
            for (int ii = lane; ii < tw; ii += 32) {
                int gi = wrap_idx(bx + ii);
                float v = 0.0f;
                if (rnz && (unsigned)(gi - PB) < (unsigned)HN) v = __ldg(rp + gi);
                trow[ii] = v;
            }
        }
        __syncthreads();

        // ---- branch-free bilinear sampling from SMEM ----
        const float bxf = (float)bx, byf = (float)by;
        const float xof = cxk - bxf;      // fx = s*Y + xof
        const float yof = syk - byf;      // fy = c*Y + yof
        #pragma unroll
        for (int k = 0; k < 8; k++) {
            int y = ch * YT + phase + 8 * k;
            if (y < OUTW) {
                float Y  = (float)y;
                float fx = fmaf(s, Y, xof);
                float fy = fmaf(c, Y, yof);
                int ii = (int)fx;
                int jj = (int)fy;
                float dx = fx - (float)ii;
                float dy = fy - (float)jj;
                const float* p = tile + jj * tw + ii;
                float v00 = p[0], v01 = p[1];
                float v10 = p[tw], v11 = p[tw + 1];
                float top = v00 + dx * (v01 - v00);
                float bot = v10 + dx * (v11 - v10);
                acc += top + dy * (bot - top);
            }
        }
    }

    // ---- per-column reduce over 8 phases, write, global max ----
    sred[phase][col] = acc;
    __syncthreads();
    if (tid < 64) {
        float v = sred[0][tid];
        #pragma unroll
        for (int p = 1; p < 8; p++) v += sred[p][tid];
        int x = xb + tid;
        float vm = v;
        if (x < OUTW) out[(size_t)x * NA + t] = v; else vm = -INFINITY;
        unsigned key = float_key(vm);
        #pragma unroll
        for (int o = 16; o > 0; o >>= 1) {
            unsigned other = __shfl_xor_sync(0xffffffffu, key, o);
            key = key > other ? key : other;
        }
        if (lane == 0) atomicMax(&g_maxkey, key);
    }
}

// ---------------------------------------------------------------------------
__global__ void norm_kernel(float* __restrict__ out, int n) {
    int i = blockIdx.x * blockDim.x + threadIdx.x;
    unsigned key = g_maxkey;
    unsigned u = (key & 0x80000000u) ? (key ^ 0x80000000u) : ~key;
    float m = __uint_as_float(u);
    if (i < n) out[i] = out[i] / m;
}

// ---------------------------------------------------------------------------
extern "C" void kernel_launch(void* const* d_in, const int* in_sizes, int n_in,
                              void* d_out, int out_size) {
    const float* img = (const float*)d_in[0];
    float* out = (float*)d_out;

    dwt_pad_kernel<<<(PDIM * PDIM + 255) / 256, 256>>>(img);

    dim3 grid((OUTW + XT - 1) / XT, NA);   // 23 x 64
    rotsum_tile_kernel<<<grid, 512>>>(out);

    norm_kernel<<<(out_size + 255) / 256, 256>>>(out, out_size);
}

// round 5
// speedup vs baseline: 1.0891x; 1.0891x over previous
#include <cuda_runtime.h>
#include <math.h>

// image 2048x2048 -> DWT high (stride-2, 2x2) -> 1024x1024
// pad to 1449x1449 with pad_before=212, center=724
// out[x*64 + t] = (sum_y bilinear(padded, rot_t(x,y))) / global_max, x<1448
#define MDIM  2048
#define HN    1024
#define PDIM  1449
#define PB    212
#define OUTW  1448
#define NA    64
#define CENTERF 724.0f
#define NZLO  211
#define NZSPAN 1024u
#define NITER 181      // 1448 / 8

__device__ float  g_pad[PDIM * PDIM];     // 8.4 MB padded DWT image
__device__ float4 g_quad[PDIM * PDIM];    // 33.6 MB 2x2-patch image
__device__ unsigned g_maxkey;

// ---------------------------------------------------------------------------
// Kernel A: fused DWT high-pass + zero pad; reset max key.
// ---------------------------------------------------------------------------
__global__ void dwt_pad_kernel(const float* __restrict__ img) {
    int idx = blockIdx.x * blockDim.x + threadIdx.x;
    if (idx == 0) g_maxkey = 0u;
    if (idx >= PDIM * PDIM) return;
    int py = idx / PDIM;
    int px = idx - py * PDIM;
    int iy = py - PB;
    int ix = px - PB;
    float v = 0.0f;
    if ((unsigned)iy < (unsigned)HN && (unsigned)ix < (unsigned)HN) {
        const float2* r0 = (const float2*)(img + (size_t)(2 * iy) * MDIM) + ix;
        const float2* r1 = (const float2*)((const float*)r0 + MDIM);
        float2 a = __ldg(r0);
        float2 b = __ldg(r1);
        v = -0.1384f * a.x + 0.7243f * a.y
            - 0.6038f * b.x + 0.1601f * b.y;
    }
    g_pad[idx] = v;
}

// ---------------------------------------------------------------------------
// Kernel B: pack 2x2 neighborhoods into float4 quads (one load per sample later)
// ---------------------------------------------------------------------------
__global__ void pack_quad_kernel() {
    int idx = blockIdx.x * blockDim.x + threadIdx.x;
    if (idx >= PDIM * PDIM) return;
    int py = idx / PDIM;
    int px = idx - py * PDIM;
    int px1 = (px + 1 == PDIM) ? 0 : px + 1;
    int py1 = (py + 1 == PDIM) ? 0 : py + 1;
    const float* r0 = g_pad + (size_t)py  * PDIM;
    const float* r1 = g_pad + (size_t)py1 * PDIM;
    float4 q;
    q.x = r0[px];  q.y = r0[px1];
    q.z = r1[px];  q.w = r1[px1];
    g_quad[idx] = q;
}

__device__ __forceinline__ unsigned float_key(float f) {
    unsigned u = __float_as_uint(f);
    return (u & 0x80000000u) ? ~u : (u | 0x80000000u);
}

__device__ __forceinline__ int wrap_idx(int i) {
    if (i >= PDIM) i -= PDIM;
    if (i < 0)     i += PDIM;
    return i;
}

// does unwrapped floor interval [a,b] (a > -PDIM, b < 2*PDIM) hit [211,1235] mod PDIM?
__device__ __forceinline__ bool hits_nz_rng(int a, int b) {
    return (a <= 1235 && b >= NZLO) || (a <= NZLO - PDIM + NZSPAN) /* a+1449<=1235 */
           || (b >= NZLO + PDIM);   /* b-1449 >= 211 */
}

// ---------------------------------------------------------------------------
// Rotate + column-sum. Block = 256 threads over 32 output columns; loop walks
// 181 groups of 8 consecutive Y rows. Warp micro-tile: 8x4 (|s|<=|c|) or
// 4x8 (|s|>|c|) with CONSECUTIVE Y lanes -> small footprint. One LDG.128 per
// sample via the quad image. Block-uniform bbox test skips dead row-groups.
// ---------------------------------------------------------------------------
__global__ void __launch_bounds__(256) rotsum_kernel(float* __restrict__ out) {
    const int t = blockIdx.y;
    float s, c;
    sincosf((float)t, &s, &c);
    const bool swap = fabsf(s) > fabsf(c);

    const int tid  = threadIdx.x;
    const int lane = tid & 31;
    const int w    = tid >> 5;

    int colofs, yofs;
    if (!swap) {            // 8 X x 4 Y lanes; 4x2 warps
        colofs = (w & 3) * 8 + (lane & 7);
        yofs   = (w >> 2) * 4 + (lane >> 3);
    } else {                // 4 X x 8 Y lanes; 8x1 warps
        colofs = (w & 7) * 4 + (lane & 3);
        yofs   = lane >> 2;
    }

    const int   xb  = blockIdx.x * 32;
    const int   x   = xb + colofs;
    const float kx  = CENTERF * (c + s - 1.0f);
    const float ky  = CENTERF * (c - s - 1.0f);
    const float X   = (float)x;
    const float cxk = fmaf(c, X, -kx);    // x_in = s*Y + cxk
    const float syk = fmaf(-s, X, -ky);   // y_in = c*Y + syk

    // block bbox helpers (corner X values)
    const float Xa = (float)xb, Xb = (float)(xb + 31);
    const float xA = c * Xa - kx, xB = c * Xb - kx;   // x_in at Y=0 for corners
    const float yA = -s * Xa - ky, yB = -s * Xb - ky;

    float acc = 0.0f;

    for (int it = 0; it < NITER; it++) {
        const float Ya = (float)(it * 8);
        const float Yb = Ya + 7.0f;
        // x_in / y_in extrema over the 32x8 sample group (bilinear in X,Y -> corners)
        float xmin = fminf(fminf(xA + s * Ya, xA + s * Yb), fminf(xB + s * Ya, xB + s * Yb));
        float xmax = fmaxf(fmaxf(xA + s * Ya, xA + s * Yb), fmaxf(xB + s * Ya, xB + s * Yb));
        float ymin = fminf(fminf(yA + c * Ya, yA + c * Yb), fminf(yB + c * Ya, yB + c * Yb));
        float ymax = fmaxf(fmaxf(yA + c * Ya, yA + c * Yb), fmaxf(yB + c * Ya, yB + c * Yb));
        if (!hits_nz_rng((int)floorf(xmin), (int)floorf(xmax)) ||
            !hits_nz_rng((int)floorf(ymin), (int)floorf(ymax))) continue;

        const float Y  = Ya + (float)yofs;
        const float fx = fmaf(s, Y, cxk);
        const float fy = fmaf(c, Y, syk);
        const float x0f = floorf(fx);
        const float y0f = floorf(fy);
        int x0 = wrap_idx((int)x0f);
        int y0 = wrap_idx((int)y0f);
        bool nz = ((unsigned)(x0 - NZLO) <= NZSPAN) && ((unsigned)(y0 - NZLO) <= NZSPAN);
        if (nz) {
            float dx = fx - x0f;
            float dy = fy - y0f;
            float4 q = __ldg(g_quad + (size_t)y0 * PDIM + x0);
            float top = q.x + dx * (q.y - q.x);
            float bot = q.z + dx * (q.w - q.z);
            acc += top + dy * (bot - top);
        }
    }

    // ---- per-column reduce over the 8 yofs phases ----
    __shared__ float sred[8][33];
    sred[yofs][colofs] = acc;
    __syncthreads();
    if (tid < 32) {
        float v = sred[0][tid];
        #pragma unroll
        for (int p = 1; p < 8; p++) v += sred[p][tid];
        int xo = xb + tid;
        float vm = v;
        if (xo < OUTW) out[(size_t)xo * NA + t] = v; else vm = -INFINITY;
        unsigned key = float_key(vm);
        #pragma unroll
        for (int o = 16; o > 0; o >>= 1) {
            unsigned other = __shfl_xor_sync(0xffffffffu, key, o);
            key = key > other ? key : other;
        }
        if (tid == 0) atomicMax(&g_maxkey, key);
    }
}

// ---------------------------------------------------------------------------
__global__ void norm_kernel(float* __restrict__ out, int n) {
    int i = blockIdx.x * blockDim.x + threadIdx.x;
    unsigned key = g_maxkey;
    unsigned u = (key & 0x80000000u) ? (key ^ 0x80000000u) : ~key;
    float m = __uint_as_float(u);
    if (i < n) out[i] = out[i] / m;
}

// ---------------------------------------------------------------------------
extern "C" void kernel_launch(void* const* d_in, const int* in_sizes, int n_in,
                              void* d_out, int out_size) {
    const float* img = (const float*)d_in[0];
    float* out = (float*)d_out;

    dwt_pad_kernel<<<(PDIM * PDIM + 255) / 256, 256>>>(img);
    pack_quad_kernel<<<(PDIM * PDIM + 255) / 256, 256>>>();

    dim3 grid((OUTW + 31) / 32, NA);    // 46 x 64
    rotsum_kernel<<<grid, 256>>>(out);

    norm_kernel<<<(out_size + 255) / 256, 256>>>(out, out_size);
}

// round 6
// speedup vs baseline: 1.5320x; 1.4067x over previous
#include <cuda_runtime.h>
#include <math.h>

// image 2048x2048 -> DWT high (stride-2, 2x2) -> 1024x1024
// pad to 1449x1449 with pad_before=212, center=724
// out[x*64 + t] = (sum_y bilinear(padded, rot_t(x,y))) / global_max, x<1448
#define MDIM  2048
#define HN    1024
#define PDIM  1449
#define PB    212
#define OUTW  1448
#define NA    64
#define CENTERF 724.0f
#define NZLO  211
#define NZSPAN 1024u

__device__ float  g_pad[PDIM * PDIM];     // 8.4 MB padded DWT image
__device__ float2 g_q2[PDIM * PDIM];      // 16.8 MB y-pair image: (pad[y][x], pad[y+1][x])
__device__ unsigned g_maxkey;

// ---------------------------------------------------------------------------
// Kernel A: fused DWT high-pass + zero pad (float2 reads); reset max key.
// ---------------------------------------------------------------------------
__global__ void dwt_pad_kernel(const float* __restrict__ img) {
    int idx = blockIdx.x * blockDim.x + threadIdx.x;
    if (idx == 0) g_maxkey = 0u;
    if (idx >= PDIM * PDIM) return;
    int py = idx / PDIM;
    int px = idx - py * PDIM;
    int iy = py - PB;
    int ix = px - PB;
    float v = 0.0f;
    if ((unsigned)iy < (unsigned)HN && (unsigned)ix < (unsigned)HN) {
        const float2* r0 = (const float2*)(img + (size_t)(2 * iy) * MDIM) + ix;
        const float2* r1 = (const float2*)((const float*)r0 + MDIM);
        float2 a = __ldg(r0);
        float2 b = __ldg(r1);
        v = -0.1384f * a.x + 0.7243f * a.y
            - 0.6038f * b.x + 0.1601f * b.y;
    }
    g_pad[idx] = v;
}

// ---------------------------------------------------------------------------
// Kernel B: pack vertical pairs: g_q2[y][x] = (pad[y][x], pad[y+1 mod][x]).
// ---------------------------------------------------------------------------
__global__ void pack_q2_kernel() {
    int idx = blockIdx.x * blockDim.x + threadIdx.x;
    if (idx >= PDIM * PDIM) return;
    int py = idx / PDIM;
    int px = idx - py * PDIM;
    int py1 = (py + 1 == PDIM) ? 0 : py + 1;
    float2 q;
    q.x = g_pad[(size_t)py  * PDIM + px];
    q.y = g_pad[(size_t)py1 * PDIM + px];
    g_q2[idx] = q;
}

__device__ __forceinline__ unsigned float_key(float f) {
    unsigned u = __float_as_uint(f);
    return (u & 0x80000000u) ? ~u : (u | 0x80000000u);
}

// wrap an index known to lie in (-PDIM, 2*PDIM)
__device__ __forceinline__ int wrap_idx(int i) {
    if (i >= PDIM) i -= PDIM;
    if (i < 0)     i += PDIM;
    return i;
}

// bilinear sample via y-pair image: 2x LDG.64 instead of 4x LDG.32.
// Bit-identical arithmetic to the scalar version.
__device__ __forceinline__ float sample_pad(float x_in, float y_in) {
    float x0f = floorf(x_in);
    float y0f = floorf(y_in);
    int x0 = wrap_idx((int)x0f);
    int y0 = wrap_idx((int)y0f);
    bool nz = ((unsigned)(x0 - NZLO) <= NZSPAN) && ((unsigned)(y0 - NZLO) <= NZSPAN);
    float r = 0.0f;
    if (nz) {
        // nz guarantees x0 <= 1235 -> x0+1 needs no wrap; y-wrap baked into g_q2
        float dx = x_in - x0f;
        float dy = y_in - y0f;
        const float2* __restrict__ p = g_q2 + (size_t)y0 * PDIM + x0;
        float2 q0 = __ldg(p);        // (v00, v10)
        float2 q1 = __ldg(p + 1);    // (v01, v11)
        float top = q0.x + dx * (q1.x - q0.x);
        float bot = q0.y + dx * (q1.y - q0.y);
        r = top + dy * (bot - top);
    }
    return r;
}

// ---------------------------------------------------------------------------
// Variant A: |s| <= |c|. Lane micro-tile 8(X) x 4(Y-phase); warp tiles 4(X) x 2(Y).
// Block 256 = 32 output columns x 8 Y-phases (stride 8 over 1448 rows).
// ---------------------------------------------------------------------------
__global__ void __launch_bounds__(256) rotsumA_kernel(float* __restrict__ out) {
    const int t = blockIdx.y;
    const float ang = (float)t;
    const float c = cosf(ang);
    const float s = sinf(ang);
    if (fabsf(s) > fabsf(c)) return;   // variant B owns this angle

    const int tid  = threadIdx.x;
    const int lane = tid & 31;
    const int w    = tid >> 5;
    const int lx = lane & 7;           // 8 lanes along X
    const int ly = lane >> 3;          // 4 lanes along Y-phase
    const int wx = w & 3;              // 4 warps along X
    const int wy = w >> 2;             // 2 warps along Y-phase
    const int col   = wx * 8 + lx;     // 0..31
    const int x     = blockIdx.x * 32 + col;
    const int phase = wy * 4 + ly;     // 0..7

    const float kx = CENTERF * (c + s - 1.0f);
    const float ky = CENTERF * (c - s - 1.0f);
    const float X = (float)x;
    const float cxk = fmaf(c, X, -kx);   // x_in = s*Y + cxk
    const float syk = fmaf(-s, X, -ky);  // y_in = c*Y + syk

    float acc = 0.0f;
    #pragma unroll 4
    for (int y = phase; y < OUTW; y += 8) {
        const float Y = (float)y;
        acc += sample_pad(fmaf(s, Y, cxk), fmaf(c, Y, syk));
    }

    __shared__ float sm[8][33];
    sm[phase][col] = acc;
    __syncthreads();

    if (tid < 32) {
        float v = sm[0][tid];
        #pragma unroll
        for (int p = 1; p < 8; p++) v += sm[p][tid];
        int xo = blockIdx.x * 32 + tid;
        float vm = v;
        if (xo < OUTW) out[(size_t)xo * NA + t] = v; else vm = -INFINITY;
        unsigned key = float_key(vm);
        #pragma unroll
        for (int o = 16; o > 0; o >>= 1) {
            unsigned other = __shfl_xor_sync(0xffffffffu, key, o);
            key = key > other ? key : other;
        }
        if (tid == 0) atomicMax(&g_maxkey, key);
    }
}

// ---------------------------------------------------------------------------
// Variant B: |s| > |c|. Lane micro-tile 4(X) x 8(Y-phase); 8 warps x 4 cols = 32 cols.
// Per-column reduction over the 8 Y-phase lanes via stride-4 shfl.
// ---------------------------------------------------------------------------
__global__ void __launch_bounds__(256) rotsumB_kernel(float* __restrict__ out) {
    const int t = blockIdx.y;
    const float ang = (float)t;
    const float c = cosf(ang);
    const float s = sinf(ang);
    if (fabsf(s) <= fabsf(c)) return;  // variant A owns this angle

    const int tid  = threadIdx.x;
    const int lane = tid & 31;
    const int w    = tid >> 5;
    const int lx  = lane & 3;          // 4 lanes along X
    const int lyp = lane >> 2;         // 8 lanes along Y-phase
    const int x   = blockIdx.x * 32 + w * 4 + lx;

    const float kx = CENTERF * (c + s - 1.0f);
    const float ky = CENTERF * (c - s - 1.0f);
    const float X = (float)x;
    const float cxk = fmaf(c, X, -kx);
    const float syk = fmaf(-s, X, -ky);

    float acc = 0.0f;
    #pragma unroll 4
    for (int y = lyp; y < OUTW; y += 8) {
        const float Y = (float)y;
        acc += sample_pad(fmaf(s, Y, cxk), fmaf(c, Y, syk));
    }

    // sum the 8 Y-phase lanes that share this column (bits 2..4 of lane id)
    #pragma unroll
    for (int o = 4; o < 32; o <<= 1)
        acc += __shfl_xor_sync(0xffffffffu, acc, o);

    if (lyp == 0 && x < OUTW) {
        out[(size_t)x * NA + t] = acc;
        atomicMax(&g_maxkey, float_key(acc));
    }
}

// ---------------------------------------------------------------------------
__global__ void norm_kernel(float* __restrict__ out, int n) {
    int i = blockIdx.x * blockDim.x + threadIdx.x;
    unsigned key = g_maxkey;
    unsigned u = (key & 0x80000000u) ? (key ^ 0x80000000u) : ~key;
    float m = __uint_as_float(u);
    if (i < n) out[i] = out[i] / m;
}

// ---------------------------------------------------------------------------
extern "C" void kernel_launch(void* const* d_in, const int* in_sizes, int n_in,
                              void* d_out, int out_size) {
    const float* img = (const float*)d_in[0];
    float* out = (float*)d_out;

    dwt_pad_kernel<<<(PDIM * PDIM + 255) / 256, 256>>>(img);
    pack_q2_kernel<<<(PDIM * PDIM + 255) / 256, 256>>>();

    dim3 grid((OUTW + 31) / 32, NA);
    rotsumA_kernel<<<grid, 256>>>(out);
    rotsumB_kernel<<<grid, 256>>>(out);

    norm_kernel<<<(out_size + 255) / 256, 256>>>(out, out_size);
}

// round 7
// speedup vs baseline: 1.7809x; 1.1625x over previous
#include <cuda_runtime.h>
#include <math.h>

// image 2048x2048 -> DWT high (stride-2, 2x2) -> 1024x1024
// pad to 1449x1449 with pad_before=212, center=724
// out[x*64 + t] = (sum_y bilinear(padded, rot_t(x,y))) / global_max, x<1448
#define MDIM  2048
#define HN    1024
#define PDIM  1449
#define PB    212
#define OUTW  1448
#define NA    64
#define CENTERF 724.0f

__device__ float  g_pad[PDIM * PDIM];     // 8.4 MB padded DWT image
__device__ float2 g_q2[PDIM * PDIM];      // 16.8 MB y-pair image: (pad[y][x], pad[y+1][x])
__device__ unsigned g_maxkey;

// ---------------------------------------------------------------------------
// Kernel A: fused DWT high-pass + zero pad; reset max key.
// ---------------------------------------------------------------------------
__global__ void dwt_pad_kernel(const float* __restrict__ img) {
    int idx = blockIdx.x * blockDim.x + threadIdx.x;
    if (idx == 0) g_maxkey = 0u;
    if (idx >= PDIM * PDIM) return;
    int py = idx / PDIM;
    int px = idx - py * PDIM;
    int iy = py - PB;
    int ix = px - PB;
    float v = 0.0f;
    if ((unsigned)iy < (unsigned)HN && (unsigned)ix < (unsigned)HN) {
        const float2* r0 = (const float2*)(img + (size_t)(2 * iy) * MDIM) + ix;
        const float2* r1 = (const float2*)((const float*)r0 + MDIM);
        float2 a = __ldg(r0);
        float2 b = __ldg(r1);
        v = -0.1384f * a.x + 0.7243f * a.y
            - 0.6038f * b.x + 0.1601f * b.y;
    }
    g_pad[idx] = v;
}

// ---------------------------------------------------------------------------
// Kernel B: pack vertical pairs: g_q2[y][x] = (pad[y][x], pad[y+1 mod][x]).
// ---------------------------------------------------------------------------
__global__ void pack_q2_kernel() {
    int idx = blockIdx.x * blockDim.x + threadIdx.x;
    if (idx >= PDIM * PDIM) return;
    int py = idx / PDIM;
    int px = idx - py * PDIM;
    int py1 = (py + 1 == PDIM) ? 0 : py + 1;
    float2 q;
    q.x = g_pad[(size_t)py  * PDIM + px];
    q.y = g_pad[(size_t)py1 * PDIM + px];
    g_q2[idx] = q;
}

__device__ __forceinline__ unsigned float_key(float f) {
    unsigned u = __float_as_uint(f);
    return (u & 0x80000000u) ? ~u : (u | 0x80000000u);
}

// ---------------------------------------------------------------------------
// For u(Y) = a*Y + b, compute Y-intervals (widened +-2, clamped to [0,1447])
// where floor(u) falls in the nonzero window [211,1235] + 1449*(k-1), k=0,1,2.
// Widened samples land on the zero border (contribute exactly 0, in-bounds).
// ---------------------------------------------------------------------------
__device__ __forceinline__ void window_intervals(float a, float b,
                                                 float* lo, float* hi) {
    const float ra = 1.0f / a;   // safe: handled below when |a| tiny
    #pragma unroll
    for (int k = 0; k < 3; k++) {
        float wlo = 211.0f + 1449.0f * (float)(k - 1);
        float whi = 1236.0f + 1449.0f * (float)(k - 1);
        float y0, y1;
        if (fabsf(a) < 1e-5f) {
            bool in = (b >= wlo - 2.0f) && (b < whi + 2.0f);
            lo[k] = in ? 0.0f : 1e9f;
            hi[k] = in ? 1447.0f : -1e9f;
        } else {
            y0 = (wlo - b) * ra;
            y1 = (whi - b) * ra;
            if (a < 0.0f) { float tmp = y0; y0 = y1; y1 = tmp; }
            lo[k] = fmaxf(y0 - 2.0f, 0.0f);
            hi[k] = fminf(y1 + 2.0f, 1447.0f);
        }
    }
}

// Branch-free interval-walking accumulator. x_in = s*Y + cxk, y_in = c*Y + syk.
__device__ __forceinline__ float accum_intervals(float s, float c,
                                                 float cxk, float syk,
                                                 int phase) {
    float xlo[3], xhi[3], ylo[3], yhi[3];
    window_intervals(s, cxk, xlo, xhi);
    window_intervals(c, syk, ylo, yhi);

    float acc = 0.0f;
    #pragma unroll
    for (int kx = 0; kx < 3; kx++) {
        #pragma unroll
        for (int ky = 0; ky < 3; ky++) {
            float flo = fmaxf(xlo[kx], ylo[ky]);
            float fhi = fminf(xhi[kx], yhi[ky]);
            if (flo > fhi) continue;
            // wrap offsets are constant within this intersection
            const int OFFC = -(ky - 1) * 1449 * PDIM - (kx - 1) * 1449;
            int yls = (int)ceilf(flo);
            yls += (phase - yls) & 7;            // align to y == phase (mod 8)
            const int yle = (int)floorf(fhi);
            float Yf = (float)yls;
            #pragma unroll 4
            for (int y = yls; y <= yle; y += 8, Yf += 8.0f) {
                float fx = fmaf(s, Yf, cxk);
                float fy = fmaf(c, Yf, syk);
                float xf = floorf(fx);
                float yf = floorf(fy);
                float dx = fx - xf;
                float dy = fy - yf;
                int idx = (int)yf * PDIM + (int)xf + OFFC;
                float2 q0 = __ldg(g_q2 + idx);      // (v00, v10)
                float2 q1 = __ldg(g_q2 + idx + 1);  // (v01, v11)
                float top = fmaf(dx, q1.x - q0.x, q0.x);
                float bot = fmaf(dx, q1.y - q0.y, q0.y);
                acc += fmaf(dy, bot - top, top);
            }
        }
    }
    return acc;
}

// ---------------------------------------------------------------------------
// Variant A: |s| <= |c|. Lane micro-tile 8(X) x 4(Y-phase); warp tiles 4(X) x 2(Y).
// Block 256 = 32 output columns x 8 Y-phases (stride 8 over 1448 rows).
// ---------------------------------------------------------------------------
__global__ void __launch_bounds__(256) rotsumA_kernel(float* __restrict__ out) {
    const int t = blockIdx.y;
    const float ang = (float)t;
    const float c = cosf(ang);
    const float s = sinf(ang);
    if (fabsf(s) > fabsf(c)) return;   // variant B owns this angle

    const int tid  = threadIdx.x;
    const int lane = tid & 31;
    const int w    = tid >> 5;
    const int col   = (w & 3) * 8 + (lane & 7);   // 0..31
    const int x     = blockIdx.x * 32 + col;
    const int phase = (w >> 2) * 4 + (lane >> 3); // 0..7

    const float kx = CENTERF * (c + s - 1.0f);
    const float ky = CENTERF * (c - s - 1.0f);
    const float X = (float)x;
    const float cxk = fmaf(c, X, -kx);   // x_in = s*Y + cxk
    const float syk = fmaf(-s, X, -ky);  // y_in = c*Y + syk

    float acc = accum_intervals(s, c, cxk, syk, phase);

    __shared__ float sm[8][33];
    sm[phase][col] = acc;
    __syncthreads();

    if (tid < 32) {
        float v = sm[0][tid];
        #pragma unroll
        for (int p = 1; p < 8; p++) v += sm[p][tid];
        int xo = blockIdx.x * 32 + tid;
        float vm = v;
        if (xo < OUTW) out[(size_t)xo * NA + t] = v; else vm = -INFINITY;
        unsigned key = float_key(vm);
        #pragma unroll
        for (int o = 16; o > 0; o >>= 1) {
            unsigned other = __shfl_xor_sync(0xffffffffu, key, o);
            key = key > other ? key : other;
        }
        if (tid == 0) atomicMax(&g_maxkey, key);
    }
}

// ---------------------------------------------------------------------------
// Variant B: |s| > |c|. Lane micro-tile 4(X) x 8(Y-phase); 8 warps x 4 cols.
// ---------------------------------------------------------------------------
__global__ void __launch_bounds__(256) rotsumB_kernel(float* __restrict__ out) {
    const int t = blockIdx.y;
    const float ang = (float)t;
    const float c = cosf(ang);
    const float s = sinf(ang);
    if (fabsf(s) <= fabsf(c)) return;  // variant A owns this angle

    const int tid  = threadIdx.x;
    const int lane = tid & 31;
    const int w    = tid >> 5;
    const int x     = blockIdx.x * 32 + w * 4 + (lane & 3);
    const int phase = lane >> 2;       // 0..7

    const float kx = CENTERF * (c + s - 1.0f);
    const float ky = CENTERF * (c - s - 1.0f);
    const float X = (float)x;
    const float cxk = fmaf(c, X, -kx);
    const float syk = fmaf(-s, X, -ky);

    float acc = accum_intervals(s, c, cxk, syk, phase);

    // sum the 8 Y-phase lanes that share this column (bits 2..4 of lane id)
    #pragma unroll
    for (int o = 4; o < 32; o <<= 1)
        acc += __shfl_xor_sync(0xffffffffu, acc, o);

    if (phase == 0 && x < OUTW) {
        out[(size_t)x * NA + t] = acc;
        atomicMax(&g_maxkey, float_key(acc));
    }
}

// ---------------------------------------------------------------------------
__global__ void norm_kernel(float* __restrict__ out, int n) {
    int i = blockIdx.x * blockDim.x + threadIdx.x;
    unsigned key = g_maxkey;
    unsigned u = (key & 0x80000000u) ? (key ^ 0x80000000u) : ~key;
    float m = __uint_as_float(u);
    if (i < n) out[i] = out[i] / m;
}

// ---------------------------------------------------------------------------
extern "C" void kernel_launch(void* const* d_in, const int* in_sizes, int n_in,
                              void* d_out, int out_size) {
    const float* img = (const float*)d_in[0];
    float* out = (float*)d_out;

    dwt_pad_kernel<<<(PDIM * PDIM + 255) / 256, 256>>>(img);
    pack_q2_kernel<<<(PDIM * PDIM + 255) / 256, 256>>>();

    dim3 grid((OUTW + 31) / 32, NA);
    rotsumA_kernel<<<grid, 256>>>(out);
    rotsumB_kernel<<<grid, 256>>>(out);

    norm_kernel<<<(out_size + 255) / 256, 256>>>(out, out_size);
}

// round 9
// speedup vs baseline: 2.7916x; 1.5676x over previous
#include <cuda_runtime.h>
#include <cuda_fp16.h>
#include <math.h>

// image 2048x2048 -> DWT high (stride-2, 2x2) -> 1024x1024
// pad to 1449x1449 with pad_before=212, center=724
// out[x*64 + t] = (sum_y bilinear(padded, rot_t(x,y))) / global_max, x<1448
#define MDIM  2048
#define HN    1024
#define PDIM  1449
#define PB    212
#define OUTW  1448
#define NA    64
#define CENTERF 724.0f

__device__ float g_pad[PDIM * PDIM];   // 8.4 MB padded DWT image
__device__ uint2 g_h4[PDIM * PDIM];    // 16.8 MB fp16 quad: (v00,v01 | v10,v11)
__device__ unsigned g_maxkey;

// ---------------------------------------------------------------------------
// Kernel A: fused DWT high-pass + zero pad; reset max key.
// ---------------------------------------------------------------------------
__global__ void dwt_pad_kernel(const float* __restrict__ img) {
    int idx = blockIdx.x * blockDim.x + threadIdx.x;
    if (idx == 0) g_maxkey = 0u;
    if (idx >= PDIM * PDIM) return;
    int py = idx / PDIM;
    int px = idx - py * PDIM;
    int iy = py - PB;
    int ix = px - PB;
    float v = 0.0f;
    if ((unsigned)iy < (unsigned)HN && (unsigned)ix < (unsigned)HN) {
        const float2* r0 = (const float2*)(img + (size_t)(2 * iy) * MDIM) + ix;
        const float2* r1 = (const float2*)((const float*)r0 + MDIM);
        float2 a = __ldg(r0);
        float2 b = __ldg(r1);
        v = -0.1384f * a.x + 0.7243f * a.y
            - 0.6038f * b.x + 0.1601f * b.y;
    }
    g_pad[idx] = v;
}

// ---------------------------------------------------------------------------
// Kernel B: pack 2x2 corner quads as fp16x4 (wraps baked in).
// ---------------------------------------------------------------------------
__global__ void pack_h4_kernel() {
    int idx = blockIdx.x * blockDim.x + threadIdx.x;
    if (idx >= PDIM * PDIM) return;
    int py = idx / PDIM;
    int px = idx - py * PDIM;
    int px1 = (px + 1 == PDIM) ? 0 : px + 1;
    int py1 = (py + 1 == PDIM) ? 0 : py + 1;
    const float* r0 = g_pad + (size_t)py  * PDIM;
    const float* r1 = g_pad + (size_t)py1 * PDIM;
    __half2 t = __floats2half2_rn(r0[px], r0[px1]);
    __half2 b = __floats2half2_rn(r1[px], r1[px1]);
    uint2 q;
    q.x = *(unsigned*)&t;
    q.y = *(unsigned*)&b;
    g_h4[idx] = q;
}

__device__ __forceinline__ unsigned float_key(float f) {
    unsigned u = __float_as_uint(f);
    return (u & 0x80000000u) ? ~u : (u | 0x80000000u);
}

// ---------------------------------------------------------------------------
// For u(Y) = a*Y + b, compute Y-intervals (widened +-2, clamped to [0,1447])
// where floor(u) falls in the nonzero window [211,1235] + 1449*(k-1), k=0,1,2.
// Widened samples land on the zero border (contribute exactly 0, in-bounds).
// ---------------------------------------------------------------------------
__device__ __forceinline__ void window_intervals(float a, float b,
                                                 float* lo, float* hi) {
    const float ra = 1.0f / a;
    #pragma unroll
    for (int k = 0; k < 3; k++) {
        float wlo = 211.0f + 1449.0f * (float)(k - 1);
        float whi = 1236.0f + 1449.0f * (float)(k - 1);
        if (fabsf(a) < 1e-5f) {
            bool in = (b >= wlo - 2.0f) && (b < whi + 2.0f);
            lo[k] = in ? 0.0f : 1e9f;
            hi[k] = in ? 1447.0f : -1e9f;
        } else {
            float y0 = (wlo - b) * ra;
            float y1 = (whi - b) * ra;
            if (a < 0.0f) { float tmp = y0; y0 = y1; y1 = tmp; }
            lo[k] = fmaxf(y0 - 2.0f, 0.0f);
            hi[k] = fminf(y1 + 2.0f, 1447.0f);
        }
    }
}

// Interval-walking accumulator: wrap offsets constant per intersection,
// inner loop branch-free, one LDG.64 per sample.
__device__ __forceinline__ float accum_intervals(float s, float c,
                                                 float cxk, float syk,
                                                 int phase) {
    float xlo[3], xhi[3], ylo[3], yhi[3];
    window_intervals(s, cxk, xlo, xhi);
    window_intervals(c, syk, ylo, yhi);

    float acc = 0.0f;
    #pragma unroll
    for (int kx = 0; kx < 3; kx++) {
        #pragma unroll
        for (int ky = 0; ky < 3; ky++) {
            float flo = fmaxf(xlo[kx], ylo[ky]);
            float fhi = fminf(xhi[kx], yhi[ky]);
            if (flo > fhi) continue;
            const int OFFC = -(ky - 1) * 1449 * PDIM - (kx - 1) * 1449;
            int yls = (int)ceilf(flo);
            yls += (phase - yls) & 7;            // align to y == phase (mod 8)
            const int yle = (int)floorf(fhi);
            float Yf = (float)yls;
            #pragma unroll 4
            for (int y = yls; y <= yle; y += 8, Yf += 8.0f) {
                float fx = fmaf(s, Yf, cxk);
                float fy = fmaf(c, Yf, syk);
                float xf = floorf(fx);
                float yf = floorf(fy);
                float dx = fx - xf;
                float dy = fy - yf;
                int idx = (int)yf * PDIM + (int)xf + OFFC;
                uint2 q = __ldg(g_h4 + idx);
                float2 tp = __half22float2(*(__half2*)&q.x);  // v00, v01
                float2 bt = __half22float2(*(__half2*)&q.y);  // v10, v11
                float top = fmaf(dx, tp.y - tp.x, tp.x);
                float bot = fmaf(dx, bt.y - bt.x, bt.x);
                acc += fmaf(dy, bot - top, top);
            }
        }
    }
    return acc;
}

// ---------------------------------------------------------------------------
// Single rotsum kernel. Block 256 = 32 output columns x 8 Y-phases.
// Lane micro-tile chosen per angle: 8x4 (|s|<=|c|) or 4x8 (|s|>|c|), with
// consecutive lanes along the image-row direction for small footprint.
// ---------------------------------------------------------------------------
__global__ void __launch_bounds__(256) rotsum_kernel(float* __restrict__ out) {
    const int t = blockIdx.y;
    float s, c;
    sincosf((float)t, &s, &c);
    const bool swap = fabsf(s) > fabsf(c);

    const int tid  = threadIdx.x;
    const int lane = tid & 31;
    const int w    = tid >> 5;

    int col, phase;
    if (!swap) {            // 8 X x 4 Yphase lanes; warps 4x2
        col   = (w & 3) * 8 + (lane & 7);
        phase = (w >> 2) * 4 + (lane >> 3);
    } else {                // 4 X x 8 Yphase lanes; warps 8x1
        col   = w * 4 + (lane & 3);
        phase = lane >> 2;
    }

    const int x = blockIdx.x * 32 + col;
    const float kx = CENTERF * (c + s - 1.0f);
    const float ky = CENTERF * (c - s - 1.0f);
    const float X = (float)x;
    const float cxk = fmaf(c, X, -kx);   // x_in = s*Y + cxk
    const float syk = fmaf(-s, X, -ky);  // y_in = c*Y + syk

    float acc = accum_intervals(s, c, cxk, syk, phase);

    __shared__ float sm[8][33];
    sm[phase][col] = acc;
    __syncthreads();

    if (tid < 32) {
        float v = sm[0][tid];
        #pragma unroll
        for (int p = 1; p < 8; p++) v += sm[p][tid];
        int xo = blockIdx.x * 32 + tid;
        float vm = v;
        if (xo < OUTW) out[(size_t)xo * NA + t] = v; else vm = -INFINITY;
        unsigned key = float_key(vm);
        #pragma unroll
        for (int o = 16; o > 0; o >>= 1) {
            unsigned other = __shfl_xor_sync(0xffffffffu, key, o);
            key = key > other ? key : other;
        }
        if (tid == 0) atomicMax(&g_maxkey, key);
    }
}

// ---------------------------------------------------------------------------
__global__ void norm_kernel(float* __restrict__ out, int n) {
    int i = blockIdx.x * blockDim.x + threadIdx.x;
    unsigned key = g_maxkey;
    unsigned u = (key & 0x80000000u) ? (key ^ 0x80000000u) : ~key;
    float m = __uint_as_float(u);
    if (i < n) out[i] = out[i] / m;
}

// ---------------------------------------------------------------------------
extern "C" void kernel_launch(void* const* d_in, const int* in_sizes, int n_in,
                              void* d_out, int out_size) {
    const float* img = (const float*)d_in[0];
    float* out = (float*)d_out;

    dwt_pad_kernel<<<(PDIM * PDIM + 255) / 256, 256>>>(img);
    pack_h4_kernel<<<(PDIM * PDIM + 255) / 256, 256>>>();

    dim3 grid((OUTW + 31) / 32, NA);
    rotsum_kernel<<<grid, 256>>>(out);

    norm_kernel<<<(out_size + 255) / 256, 256>>>(out, out_size);
}

// round 11
// speedup vs baseline: 3.2470x; 1.1631x over previous
#include <cuda_runtime.h>
#include <cuda_fp16.h>
#include <math.h>

// image 2048x2048 -> DWT high (stride-2, 2x2) -> 1024x1024
// pad to 1449x1449 with pad_before=212, center=724
// out[x*64 + t] = (sum_y bilinear(padded, rot_t(x,y))) / global_max, x<1448
#define MDIM  2048
#define HN    1024
#define PDIM  1449
#define PB    212
#define OUTW  1448
#define NA    64
#define CENTERF 724.0f

// rotsum touches quad indices only in [208,1240]^2; prep covers [200,1250)^2.
#define RLO   200
#define RSPAN 1050   // dwt region width
#define QSPAN 1048   // pack region width (needs pad up to RLO+QSPAN = 1248)

__device__ float g_pad[PDIM * PDIM];   // 8.4 MB padded DWT image
__device__ uint2 g_h4[PDIM * PDIM];    // fp16 quad, column pairs: (v00,v10 | v01,v11)
__device__ unsigned g_maxkey;

// ---------------------------------------------------------------------------
// Kernel A: fused DWT high-pass + zero pad over the live region only.
// ---------------------------------------------------------------------------
__global__ void dwt_pad_kernel(const float* __restrict__ img) {
    int px = RLO + blockIdx.x * 32 + threadIdx.x;
    int py = RLO + blockIdx.y * 8 + threadIdx.y;
    if (blockIdx.x == 0 && blockIdx.y == 0 && threadIdx.x == 0 && threadIdx.y == 0)
        g_maxkey = 0u;
    if (px >= RLO + RSPAN || py >= RLO + RSPAN) return;
    int iy = py - PB;
    int ix = px - PB;
    float v = 0.0f;
    if ((unsigned)iy < (unsigned)HN && (unsigned)ix < (unsigned)HN) {
        const float2* r0 = (const float2*)(img + (size_t)(2 * iy) * MDIM) + ix;
        const float2* r1 = (const float2*)((const float*)r0 + MDIM);
        float2 a = __ldg(r0);
        float2 b = __ldg(r1);
        v = -0.1384f * a.x + 0.7243f * a.y
            - 0.6038f * b.x + 0.1601f * b.y;
    }
    g_pad[py * PDIM + px] = v;
}

// ---------------------------------------------------------------------------
// Kernel B: pack 2x2 corner quads as fp16 COLUMN pairs over the live region.
// q.x = (v00, v10) at column x; q.y = (v01, v11) at column x+1.
// ---------------------------------------------------------------------------
__global__ void pack_h4_kernel() {
    int px = RLO + blockIdx.x * 32 + threadIdx.x;
    int py = RLO + blockIdx.y * 8 + threadIdx.y;
    if (px >= RLO + QSPAN || py >= RLO + QSPAN) return;
    const float* r0 = g_pad + py * PDIM;
    const float* r1 = r0 + PDIM;
    __half2 c0 = __floats2half2_rn(r0[px],     r1[px]);      // v00, v10
    __half2 c1 = __floats2half2_rn(r0[px + 1], r1[px + 1]);  // v01, v11
    uint2 q;
    q.x = *(unsigned*)&c0;
    q.y = *(unsigned*)&c1;
    g_h4[py * PDIM + px] = q;
}

__device__ __forceinline__ unsigned float_key(float f) {
    unsigned u = __float_as_uint(f);
    return (u & 0x80000000u) ? ~u : (u | 0x80000000u);
}

// ---------------------------------------------------------------------------
// For u(Y) = a*Y + b, compute Y-intervals (widened +-2, clamped to [0,1447])
// where floor(u) falls in the nonzero window [211,1235] + 1449*(k-1), k=0,1,2.
// Widened samples land on the zero border (contribute exactly 0, in-bounds).
// ---------------------------------------------------------------------------
__device__ __forceinline__ void window_intervals(float a, float b,
                                                 float* lo, float* hi) {
    const float ra = 1.0f / a;
    #pragma unroll
    for (int k = 0; k < 3; k++) {
        float wlo = 211.0f + 1449.0f * (float)(k - 1);
        float whi = 1236.0f + 1449.0f * (float)(k - 1);
        if (fabsf(a) < 1e-5f) {
            bool in = (b >= wlo - 2.0f) && (b < whi + 2.0f);
            lo[k] = in ? 0.0f : 1e9f;
            hi[k] = in ? 1447.0f : -1e9f;
        } else {
            float y0 = (wlo - b) * ra;
            float y1 = (whi - b) * ra;
            if (a < 0.0f) { float tmp = y0; y0 = y1; y1 = tmp; }
            lo[k] = fmaxf(y0 - 2.0f, 0.0f);
            hi[k] = fminf(y1 + 2.0f, 1447.0f);
        }
    }
}

// Interval-walking accumulator: wrap offsets constant per intersection,
// inner loop branch-free: 1 LDG.64 + HSUB2/HFMA2 interp per sample.
__device__ __forceinline__ float accum_intervals(float s, float c,
                                                 float cxk, float syk,
                                                 int phase) {
    float xlo[3], xhi[3], ylo[3], yhi[3];
    window_intervals(s, cxk, xlo, xhi);
    window_intervals(c, syk, ylo, yhi);

    float acc = 0.0f;
    #pragma unroll
    for (int kx = 0; kx < 3; kx++) {
        #pragma unroll
        for (int ky = 0; ky < 3; ky++) {
            float flo = fmaxf(xlo[kx], ylo[ky]);
            float fhi = fminf(xhi[kx], yhi[ky]);
            if (flo > fhi) continue;
            const int OFFC = -(ky - 1) * 1449 * PDIM - (kx - 1) * 1449;
            int yls = (int)ceilf(flo);
            yls += (phase - yls) & 7;            // align to y == phase (mod 8)
            const int yle = (int)floorf(fhi);
            float Yf = (float)yls;
            #pragma unroll 4
            for (int y = yls; y <= yle; y += 8, Yf += 8.0f) {
                float fx = fmaf(s, Yf, cxk);
                float fy = fmaf(c, Yf, syk);
                int xi = __float2int_rd(fx);
                int yi = __float2int_rd(fy);
                float dx = fx - (float)xi;
                float dy = fy - (float)yi;
                int idx = yi * PDIM + xi + OFFC;
                uint2 q = __ldg(g_h4 + idx);
                __half2 q0 = *(__half2*)&q.x;            // (v00, v10)
                __half2 q1 = *(__half2*)&q.y;            // (v01, v11)
                __half2 tb = __hfma2(__float2half2_rn(dx),
                                     __hsub2(q1, q0), q0);  // (top, bot)
                float2 tf = __half22float2(tb);
                acc += fmaf(dy, tf.y - tf.x, tf.x);
            }
        }
    }
    return acc;
}

// ---------------------------------------------------------------------------
// Single rotsum kernel. Block 256 = 32 output columns x 8 Y-phases.
// Lane micro-tile chosen per angle: 8x4 (|s|<=|c|) or 4x8 (|s|>|c|).
// ---------------------------------------------------------------------------
__global__ void __launch_bounds__(256) rotsum_kernel(float* __restrict__ out) {
    const int t = blockIdx.y;
    float s, c;
    sincosf((float)t, &s, &c);
    const bool swap = fabsf(s) > fabsf(c);

    const int tid  = threadIdx.x;
    const int lane = tid & 31;
    const int w    = tid >> 5;

    int col, phase;
    if (!swap) {            // 8 X x 4 Yphase lanes; warps 4x2
        col   = (w & 3) * 8 + (lane & 7);
        phase = (w >> 2) * 4 + (lane >> 3);
    } else {                // 4 X x 8 Yphase lanes; warps 8x1
        col   = w * 4 + (lane & 3);
        phase = lane >> 2;
    }

    const int x = blockIdx.x * 32 + col;
    const float kx = CENTERF * (c + s - 1.0f);
    const float ky = CENTERF * (c - s - 1.0f);
    const float X = (float)x;
    const float cxk = fmaf(c, X, -kx);   // x_in = s*Y + cxk
    const float syk = fmaf(-s, X, -ky);  // y_in = c*Y + syk

    float acc = accum_intervals(s, c, cxk, syk, phase);

    __shared__ float sm[8][33];
    sm[phase][col] = acc;
    __syncthreads();

    if (tid < 32) {
        float v = sm[0][tid];
        #pragma unroll
        for (int p = 1; p < 8; p++) v += sm[p][tid];
        int xo = blockIdx.x * 32 + tid;
        float vm = v;
        if (xo < OUTW) out[(size_t)xo * NA + t] = v; else vm = -INFINITY;
        unsigned key = float_key(vm);
        #pragma unroll
        for (int o = 16; o > 0; o >>= 1) {
            unsigned other = __shfl_xor_sync(0xffffffffu, key, o);
            key = key > other ? key : other;
        }
        if (tid == 0) atomicMax(&g_maxkey, key);
    }
}

// ---------------------------------------------------------------------------
__global__ void norm_kernel(float* __restrict__ out, int n) {
    int i = blockIdx.x * blockDim.x + threadIdx.x;
    unsigned key = g_maxkey;
    unsigned u = (key & 0x80000000u) ? (key ^ 0x80000000u) : ~key;
    float m = __uint_as_float(u);
    if (i < n) out[i] = out[i] / m;
}

// ---------------------------------------------------------------------------
extern "C" void kernel_launch(void* const* d_in, const int* in_sizes, int n_in,
                              void* d_out, int out_size) {
    const float* img = (const float*)d_in[0];
    float* out = (float*)d_out;

    dim3 pb(32, 8);
    dim3 pgd((RSPAN + 31) / 32, (RSPAN + 7) / 8);
    dwt_pad_kernel<<<pgd, pb>>>(img);
    dim3 pgq((QSPAN + 31) / 32, (QSPAN + 7) / 8);
    pack_h4_kernel<<<pgq, pb>>>();

    dim3 grid((OUTW + 31) / 32, NA);
    rotsum_kernel<<<grid, 256>>>(out);

    norm_kernel<<<(out_size + 255) / 256, 256>>>(out, out_size);
}

// round 12
// speedup vs baseline: 3.3625x; 1.0356x over previous
#include <cuda_runtime.h>
#include <cuda_fp16.h>
#include <math.h>
#include <stdint.h>

// image 2048x2048 -> DWT high (stride-2, 2x2) -> 1024x1024
// pad to 1449x1449 with pad_before=212, center=724
// out[x*64 + t] = (sum_y bilinear(padded, rot_t(x,y))) / global_max, x<1448
#define MDIM  2048
#define HN    1024
#define PDIM  1449
#define PB    212
#define OUTW  1448
#define NA    64
#define CENTERF 724.0f

// rotsum touches quad indices only in [208,1240]^2; prep covers [200,1248)^2.
#define RLO   200
#define QSPAN 1048

__device__ uint2 g_h4[PDIM * PDIM];    // fp16 quad, column pairs: (v00,v10 | v01,v11)
__device__ unsigned g_maxkey;

#define PACK_F32X2(out, lo, hi) \
    asm("mov.b64 %0, {%1, %2};" : "=l"(out) : "f"(lo), "f"(hi))
#define UNPACK_F32X2(lo, hi, in) \
    asm("mov.b64 {%0, %1}, %2;" : "=f"(lo), "=f"(hi) : "l"(in))
#define FMA_F32X2(out, a, b, c) \
    asm("fma.rn.f32x2 %0, %1, %2, %3;" : "=l"(out) : "l"(a), "l"(b), "l"(c))
#define ADD_F32X2(out, a, b) \
    asm("add.rn.f32x2 %0, %1, %2;" : "=l"(out) : "l"(a), "l"(b))

// ---------------------------------------------------------------------------
// DWT high-pass value at (iy, ix); zero outside [0,1024)^2.
// ---------------------------------------------------------------------------
__device__ __forceinline__ float dwt_at(const float* __restrict__ img,
                                        int iy, int ix) {
    if ((unsigned)iy >= (unsigned)HN || (unsigned)ix >= (unsigned)HN) return 0.0f;
    const float2* r0 = (const float2*)(img + (size_t)(2 * iy) * MDIM) + ix;
    float2 a = __ldg(r0);
    float2 b = __ldg((const float2*)((const float*)r0 + MDIM));
    return -0.1384f * a.x + 0.7243f * a.y
           - 0.6038f * b.x + 0.1601f * b.y;
}

// ---------------------------------------------------------------------------
// Fused prep: compute the 2x2 DWT corner quad directly from img, pack fp16
// column pairs: q.x = (v00, v10), q.y = (v01, v11). Also resets max key.
// ---------------------------------------------------------------------------
__global__ void prep_kernel(const float* __restrict__ img) {
    int px = RLO + blockIdx.x * 32 + threadIdx.x;
    int py = RLO + blockIdx.y * 8 + threadIdx.y;
    if (blockIdx.x == 0 && blockIdx.y == 0 && threadIdx.x == 0 && threadIdx.y == 0)
        g_maxkey = 0u;
    if (px >= RLO + QSPAN || py >= RLO + QSPAN) return;
    int iy = py - PB;
    int ix = px - PB;
    float v00 = dwt_at(img, iy,     ix);
    float v01 = dwt_at(img, iy,     ix + 1);
    float v10 = dwt_at(img, iy + 1, ix);
    float v11 = dwt_at(img, iy + 1, ix + 1);
    __half2 c0 = __floats2half2_rn(v00, v10);
    __half2 c1 = __floats2half2_rn(v01, v11);
    uint2 q;
    q.x = *(unsigned*)&c0;
    q.y = *(unsigned*)&c1;
    g_h4[py * PDIM + px] = q;
}

__device__ __forceinline__ unsigned float_key(float f) {
    unsigned u = __float_as_uint(f);
    return (u & 0x80000000u) ? ~u : (u | 0x80000000u);
}

// ---------------------------------------------------------------------------
// For u(Y) = a*Y + b, compute Y-intervals (widened +-2, clamped to [0,1447])
// where floor(u) falls in the nonzero window [211,1235] + 1449*(k-1), k=0,1,2.
// Widened samples land on the zero border (contribute exactly 0, in-bounds).
// ---------------------------------------------------------------------------
__device__ __forceinline__ void window_intervals(float a, float b,
                                                 float* lo, float* hi) {
    const float ra = 1.0f / a;
    #pragma unroll
    for (int k = 0; k < 3; k++) {
        float wlo = 211.0f + 1449.0f * (float)(k - 1);
        float whi = 1236.0f + 1449.0f * (float)(k - 1);
        if (fabsf(a) < 1e-5f) {
            bool in = (b >= wlo - 2.0f) && (b < whi + 2.0f);
            lo[k] = in ? 0.0f : 1e9f;
            hi[k] = in ? 1447.0f : -1e9f;
        } else {
            float y0 = (wlo - b) * ra;
            float y1 = (whi - b) * ra;
            if (a < 0.0f) { float tmp = y0; y0 = y1; y1 = tmp; }
            lo[k] = fmaxf(y0 - 2.0f, 0.0f);
            hi[k] = fminf(y1 + 2.0f, 1447.0f);
        }
    }
}

// Interval-walking accumulator. Inner loop: packed f32x2 coordinate math,
// 1 LDG.64, half2 x-lerp, fp32 y-lerp. Branch-free per sample.
__device__ __forceinline__ float accum_intervals(float s, float c,
                                                 float cxk, float syk,
                                                 int phase) {
    float xlo[3], xhi[3], ylo[3], yhi[3];
    window_intervals(s, cxk, xlo, xhi);
    window_intervals(c, syk, ylo, yhi);

    uint64_t sc, basep, step8, neg1;
    PACK_F32X2(sc, s, c);
    PACK_F32X2(basep, cxk, syk);
    { float e = 8.0f;  PACK_F32X2(step8, e, e); }
    { float m = -1.0f; PACK_F32X2(neg1, m, m); }

    float acc = 0.0f;
    #pragma unroll
    for (int kx = 0; kx < 3; kx++) {
        #pragma unroll
        for (int ky = 0; ky < 3; ky++) {
            float flo = fmaxf(xlo[kx], ylo[ky]);
            float fhi = fminf(xhi[kx], yhi[ky]);
            if (flo > fhi) continue;
            const int OFFC = -(ky - 1) * 1449 * PDIM - (kx - 1) * 1449;
            int yls = (int)ceilf(flo);
            yls += (phase - yls) & 7;            // align to y == phase (mod 8)
            const int yle = (int)floorf(fhi);
            const int n = (yle - yls) >> 3;      // iterations - 1 (if yls<=yle)
            if (yls > yle) continue;
            uint64_t Yp;
            { float Yf = (float)yls; PACK_F32X2(Yp, Yf, Yf); }
            const uint2* __restrict__ bp = g_h4 + OFFC;
            #pragma unroll 4
            for (int i = 0; i <= n; i++) {
                uint64_t fxy, dxy, ifp;
                FMA_F32X2(fxy, sc, Yp, basep);      // (fx, fy)
                float fx, fy;
                UNPACK_F32X2(fx, fy, fxy);
                int xi = __float2int_rd(fx);
                int yi = __float2int_rd(fy);
                float xf = (float)xi, yf = (float)yi;
                PACK_F32X2(ifp, xf, yf);
                FMA_F32X2(dxy, ifp, neg1, fxy);     // (dx, dy)
                float dx, dy;
                UNPACK_F32X2(dx, dy, dxy);
                ADD_F32X2(Yp, Yp, step8);
                uint2 q = __ldg(bp + yi * PDIM + xi);
                __half2 q0 = *(__half2*)&q.x;            // (v00, v10)
                __half2 q1 = *(__half2*)&q.y;            // (v01, v11)
                __half2 tb = __hfma2(__float2half2_rn(dx),
                                     __hsub2(q1, q0), q0);  // (top, bot)
                float2 tf = __half22float2(tb);
                acc += fmaf(dy, tf.y - tf.x, tf.x);
            }
        }
    }
    return acc;
}

// ---------------------------------------------------------------------------
// Single rotsum kernel. Block 256 = 32 output columns x 8 Y-phases.
// Lane micro-tile chosen per angle: 8x4 (|s|<=|c|) or 4x8 (|s|>|c|).
// ---------------------------------------------------------------------------
__global__ void __launch_bounds__(256) rotsum_kernel(float* __restrict__ out) {
    const int t = blockIdx.y;
    float s, c;
    sincosf((float)t, &s, &c);
    const bool swap = fabsf(s) > fabsf(c);

    const int tid  = threadIdx.x;
    const int lane = tid & 31;
    const int w    = tid >> 5;

    int col, phase;
    if (!swap) {            // 8 X x 4 Yphase lanes; warps 4x2
        col   = (w & 3) * 8 + (lane & 7);
        phase = (w >> 2) * 4 + (lane >> 3);
    } else {                // 4 X x 8 Yphase lanes; warps 8x1
        col   = w * 4 + (lane & 3);
        phase = lane >> 2;
    }

    const int x = blockIdx.x * 32 + col;
    const float kx = CENTERF * (c + s - 1.0f);
    const float ky = CENTERF * (c - s - 1.0f);
    const float X = (float)x;
    const float cxk = fmaf(c, X, -kx);   // x_in = s*Y + cxk
    const float syk = fmaf(-s, X, -ky);  // y_in = c*Y + syk

    float acc = accum_intervals(s, c, cxk, syk, phase);

    __shared__ float sm[8][33];
    sm[phase][col] = acc;
    __syncthreads();

    if (tid < 32) {
        float v = sm[0][tid];
        #pragma unroll
        for (int p = 1; p < 8; p++) v += sm[p][tid];
        int xo = blockIdx.x * 32 + tid;
        float vm = v;
        if (xo < OUTW) out[(size_t)xo * NA + t] = v; else vm = -INFINITY;
        unsigned key = float_key(vm);
        #pragma unroll
        for (int o = 16; o > 0; o >>= 1) {
            unsigned other = __shfl_xor_sync(0xffffffffu, key, o);
            key = key > other ? key : other;
        }
        if (tid == 0) atomicMax(&g_maxkey, key);
    }
}

// ---------------------------------------------------------------------------
__global__ void norm_kernel(float* __restrict__ out, int n) {
    int i = blockIdx.x * blockDim.x + threadIdx.x;
    unsigned key = g_maxkey;
    unsigned u = (key & 0x80000000u) ? (key ^ 0x80000000u) : ~key;
    float m = __uint_as_float(u);
    if (i < n) out[i] = out[i] / m;
}

// ---------------------------------------------------------------------------
extern "C" void kernel_launch(void* const* d_in, const int* in_sizes, int n_in,
                              void* d_out, int out_size) {
    const float* img = (const float*)d_in[0];
    float* out = (float*)d_out;

    dim3 pb(32, 8);
    dim3 pg((QSPAN + 31) / 32, (QSPAN + 7) / 8);
    prep_kernel<<<pg, pb>>>(img);

    dim3 grid((OUTW + 31) / 32, NA);
    rotsum_kernel<<<grid, 256>>>(out);

    norm_kernel<<<(out_size + 255) / 256, 256>>>(out, out_size);
}

// round 13
// speedup vs baseline: 3.4877x; 1.0372x over previous
#include <cuda_runtime.h>
#include <cuda_fp16.h>
#include <math.h>
#include <stdint.h>

// image 2048x2048 -> DWT high (stride-2, 2x2) -> 1024x1024
// pad to 1449x1449 with pad_before=212, center=724
// out[x*64 + t] = (sum_y bilinear(padded, rot_t(x,y))) / global_max, x<1448
#define MDIM  2048
#define HN    1024
#define PDIM  1449
#define PB    212
#define OUTW  1448
#define NA    64
#define CENTERF 724.0f

// rotsum touches quad indices only in [208,1240]^2; prep covers [200,1248)^2.
#define RLO   200
#define QSPAN 1048

__device__ uint2 g_h4[PDIM * PDIM];    // fp16 quad, column pairs: (v00,v10 | v01,v11)
__device__ unsigned g_maxkey;

#define PACK_F32X2(out, lo, hi) \
    asm("mov.b64 %0, {%1, %2};" : "=l"(out) : "f"(lo), "f"(hi))
#define UNPACK_F32X2(lo, hi, in) \
    asm("mov.b64 {%0, %1}, %2;" : "=f"(lo), "=f"(hi) : "l"(in))
#define FMA_F32X2(out, a, b, c) \
    asm("fma.rn.f32x2 %0, %1, %2, %3;" : "=l"(out) : "l"(a), "l"(b), "l"(c))
#define ADD_F32X2(out, a, b) \
    asm("add.rn.f32x2 %0, %1, %2;" : "=l"(out) : "l"(a), "l"(b))

// ---------------------------------------------------------------------------
// DWT high-pass value at (iy, ix); zero outside [0,1024)^2.
// ---------------------------------------------------------------------------
__device__ __forceinline__ float dwt_at(const float* __restrict__ img,
                                        int iy, int ix) {
    if ((unsigned)iy >= (unsigned)HN || (unsigned)ix >= (unsigned)HN) return 0.0f;
    const float2* r0 = (const float2*)(img + (size_t)(2 * iy) * MDIM) + ix;
    float2 a = __ldg(r0);
    float2 b = __ldg((const float2*)((const float*)r0 + MDIM));
    return -0.1384f * a.x + 0.7243f * a.y
           - 0.6038f * b.x + 0.1601f * b.y;
}

// ---------------------------------------------------------------------------
// Fused prep: compute the 2x2 DWT corner quad directly from img, pack fp16
// column pairs: q.x = (v00, v10), q.y = (v01, v11). Also resets max key.
// ---------------------------------------------------------------------------
__global__ void prep_kernel(const float* __restrict__ img) {
    int px = RLO + blockIdx.x * 32 + threadIdx.x;
    int py = RLO + blockIdx.y * 8 + threadIdx.y;
    if (blockIdx.x == 0 && blockIdx.y == 0 && threadIdx.x == 0 && threadIdx.y == 0)
        g_maxkey = 0u;
    if (px >= RLO + QSPAN || py >= RLO + QSPAN) return;
    int iy = py - PB;
    int ix = px - PB;
    float v00 = dwt_at(img, iy,     ix);
    float v01 = dwt_at(img, iy,     ix + 1);
    float v10 = dwt_at(img, iy + 1, ix);
    float v11 = dwt_at(img, iy + 1, ix + 1);
    __half2 c0 = __floats2half2_rn(v00, v10);
    __half2 c1 = __floats2half2_rn(v01, v11);
    uint2 q;
    q.x = *(unsigned*)&c0;
    q.y = *(unsigned*)&c1;
    g_h4[py * PDIM + px] = q;
}

__device__ __forceinline__ unsigned float_key(float f) {
    unsigned u = __float_as_uint(f);
    return (u & 0x80000000u) ? ~u : (u | 0x80000000u);
}

// ---------------------------------------------------------------------------
// For u(Y) = a*Y + b, compute Y-intervals (widened +-2, clamped to [0,1447])
// where floor(u) falls in the nonzero window [211,1235] + 1449*(k-1), k=0,1,2.
// Widened samples land on the zero border (contribute exactly 0, in-bounds).
// ---------------------------------------------------------------------------
__device__ __forceinline__ void window_intervals(float a, float b,
                                                 float* lo, float* hi) {
    const float ra = 1.0f / a;
    #pragma unroll
    for (int k = 0; k < 3; k++) {
        float wlo = 211.0f + 1449.0f * (float)(k - 1);
        float whi = 1236.0f + 1449.0f * (float)(k - 1);
        if (fabsf(a) < 1e-5f) {
            bool in = (b >= wlo - 2.0f) && (b < whi + 2.0f);
            lo[k] = in ? 0.0f : 1e9f;
            hi[k] = in ? 1447.0f : -1e9f;
        } else {
            float y0 = (wlo - b) * ra;
            float y1 = (whi - b) * ra;
            if (a < 0.0f) { float tmp = y0; y0 = y1; y1 = tmp; }
            lo[k] = fmaxf(y0 - 2.0f, 0.0f);
            hi[k] = fminf(y1 + 2.0f, 1447.0f);
        }
    }
}

// Interval-walking accumulator, y-stride 16 (phase in 0..15).
// Inner loop: packed f32x2 coord math, 1 LDG.64, half2 x-lerp, fp32 y-lerp.
__device__ __forceinline__ float accum_intervals(float s, float c,
                                                 float cxk, float syk,
                                                 int phase) {
    float xlo[3], xhi[3], ylo[3], yhi[3];
    window_intervals(s, cxk, xlo, xhi);
    window_intervals(c, syk, ylo, yhi);

    uint64_t sc, basep, step16, neg1;
    PACK_F32X2(sc, s, c);
    PACK_F32X2(basep, cxk, syk);
    { float e = 16.0f; PACK_F32X2(step16, e, e); }
    { float m = -1.0f; PACK_F32X2(neg1, m, m); }

    float acc = 0.0f;
    #pragma unroll
    for (int kx = 0; kx < 3; kx++) {
        #pragma unroll
        for (int ky = 0; ky < 3; ky++) {
            float flo = fmaxf(xlo[kx], ylo[ky]);
            float fhi = fminf(xhi[kx], yhi[ky]);
            if (flo > fhi) continue;
            const int OFFC = -(ky - 1) * 1449 * PDIM - (kx - 1) * 1449;
            int yls = (int)ceilf(flo);
            yls += (phase - yls) & 15;           // align to y == phase (mod 16)
            const int yle = (int)floorf(fhi);
            if (yls > yle) continue;
            const int n = (yle - yls) >> 4;      // iterations - 1
            uint64_t Yp;
            { float Yf = (float)yls; PACK_F32X2(Yp, Yf, Yf); }
            const uint2* __restrict__ bp = g_h4 + OFFC;
            #pragma unroll 4
            for (int i = 0; i <= n; i++) {
                uint64_t fxy, dxy, ifp;
                FMA_F32X2(fxy, sc, Yp, basep);      // (fx, fy)
                float fx, fy;
                UNPACK_F32X2(fx, fy, fxy);
                int xi = __float2int_rd(fx);
                int yi = __float2int_rd(fy);
                float xf = (float)xi, yf = (float)yi;
                PACK_F32X2(ifp, xf, yf);
                FMA_F32X2(dxy, ifp, neg1, fxy);     // (dx, dy)
                float dx, dy;
                UNPACK_F32X2(dx, dy, dxy);
                ADD_F32X2(Yp, Yp, step16);
                uint2 q = __ldg(bp + yi * PDIM + xi);
                __half2 q0 = *(__half2*)&q.x;            // (v00, v10)
                __half2 q1 = *(__half2*)&q.y;            // (v01, v11)
                __half2 tb = __hfma2(__float2half2_rn(dx),
                                     __hsub2(q1, q0), q0);  // (top, bot)
                float2 tf = __half22float2(tb);
                acc += fmaf(dy, tf.y - tf.x, tf.x);
            }
        }
    }
    return acc;
}

// ---------------------------------------------------------------------------
// Rotsum: 512 threads = 32 output columns x 16 Y-phases. Warp lane micro-tile
// shape (la x lb, la*lb=32) chosen per angle to minimize image rows touched
// per warp access: rows ~= la*|s| + lb*|c|. Shapes: 16x2, 8x4, 4x8, 2x16.
// ---------------------------------------------------------------------------
__global__ void __launch_bounds__(512) rotsum_kernel(float* __restrict__ out) {
    const int t = blockIdx.y;
    float s, c;
    sincosf((float)t, &s, &c);
    const float as = fabsf(s), ac = fabsf(c);

    // pick la from {16,8,4,2} minimizing la*as + (32/la)*ac   (block-uniform)
    float best = 1e30f;
    int la = 8;
    #pragma unroll
    for (int k = 1; k <= 4; k++) {
        int cand = 1 << k;                   // 2,4,8,16
        float cost = (float)cand * as + (32.0f / (float)cand) * ac;
        if (cost < best) { best = cost; la = cand; }
    }
    const int lashift = (la == 16) ? 4 : (la == 8) ? 3 : (la == 4) ? 2 : 1;
    const int lb = 32 >> lashift;            // lanes along phase
    const int wa = 32 >> lashift;            // warps along X = 32/la
    const int washift = 5 - lashift;

    const int tid  = threadIdx.x;
    const int lane = tid & 31;
    const int w    = tid >> 5;               // 16 warps

    const int col   = ((w & (wa - 1)) << lashift) + (lane & (la - 1));
    const int phase = ((w >> washift) * lb) + (lane >> lashift);   // 0..15

    const int x = blockIdx.x * 32 + col;
    const float kx = CENTERF * (c + s - 1.0f);
    const float ky = CENTERF * (c - s - 1.0f);
    const float X = (float)x;
    const float cxk = fmaf(c, X, -kx);   // x_in = s*Y + cxk
    const float syk = fmaf(-s, X, -ky);  // y_in = c*Y + syk

    float acc = accum_intervals(s, c, cxk, syk, phase);

    __shared__ float sm[16][33];
    sm[phase][col] = acc;
    __syncthreads();

    if (tid < 32) {
        float v = sm[0][tid];
        #pragma unroll
        for (int p = 1; p < 16; p++) v += sm[p][tid];
        int xo = blockIdx.x * 32 + tid;
        float vm = v;
        if (xo < OUTW) out[(size_t)xo * NA + t] = v; else vm = -INFINITY;
        unsigned key = float_key(vm);
        #pragma unroll
        for (int o = 16; o > 0; o >>= 1) {
            unsigned other = __shfl_xor_sync(0xffffffffu, key, o);
            key = key > other ? key : other;
        }
        if (tid == 0) atomicMax(&g_maxkey, key);
    }
}

// ---------------------------------------------------------------------------
__global__ void norm_kernel(float* __restrict__ out, int n) {
    int i = blockIdx.x * blockDim.x + threadIdx.x;
    unsigned key = g_maxkey;
    unsigned u = (key & 0x80000000u) ? (key ^ 0x80000000u) : ~key;
    float m = __uint_as_float(u);
    if (i < n) out[i] = out[i] / m;
}

// ---------------------------------------------------------------------------
extern "C" void kernel_launch(void* const* d_in, const int* in_sizes, int n_in,
                              void* d_out, int out_size) {
    const float* img = (const float*)d_in[0];
    float* out = (float*)d_out;

    dim3 pb(32, 8);
    dim3 pg((QSPAN + 31) / 32, (QSPAN + 7) / 8);
    prep_kernel<<<pg, pb>>>(img);

    dim3 grid((OUTW + 31) / 32, NA);
    rotsum_kernel<<<grid, 512>>>(out);

    norm_kernel<<<(out_size + 255) / 256, 256>>>(out, out_size);
}